// round 11
// baseline (speedup 1.0000x reference)
#include <cuda_runtime.h>
#include <cuda_fp16.h>
#include <mma.h>
#include <math.h>

using namespace nvcuda;

#define NN 50000
#define NE 800000
#define NG 500
#define CC 64
#define NL 13          // 1 + 12 PDN convs
#define LSTRIDE 292    // per-layer smem stride (half2 entries) for edge MLP weights

// modes for k_agg epilogue
#define M_COPY  1
#define M_SKIP  2
#define M_POOL  8
#define M_STATS 16

// ---------------- scratch (device globals; no allocation) ----------------
__device__ __half g_h  [NN*CC];     // fp16 GEMM output (gather bandwidth halved)
__device__ float  g_cur[NN*CC];
__device__ float  g_acc[NN*CC];
__device__ float  g_ew [NL*NE];     // raw ew (CSR order) -> scaled to ew*dis_src in k_norm
__device__ float  g_deg[NN*16];     // [node][16] deg -> rsqrt(deg) in place (k_rsqrt)
__device__ int    g_cnt[NN];        // zero at entry (static init / re-zeroed by k_norm)
__device__ int    g_rowptr[NN+1];
__device__ int    g_cursor[NN];
__device__ __align__(16) int2 g_epack[NE];   // {eid, dst} in CSR order
__device__ int    g_csrc[NE];
__device__ float  g_colsum[13*64];  // fp32 BN stats (zeroed in k_scanall)
__device__ float  g_colsq [13*64];
__device__ float  g_pool[NG*CC];    // zeroed in k_scanall

// ---------------- CSR build ----------------
// NE == 3125*256 exactly; also NE == NN*16, so this thread grid covers g_deg init.
__global__ void k_hist(const int* __restrict__ dst) {
    int e = blockIdx.x*blockDim.x + threadIdx.x;
    g_deg[e] = 1.0f;                 // deg starts at self-loop weight 1
    atomicAdd(&g_cnt[dst[e]], 1);    // g_cnt zero at entry
}

// single-block chunked scan: 1024 threads, 49 chunks; also zeroes pool/stats
__global__ void k_scanall() {
    __shared__ int wsum[32];
    int t = threadIdx.x;
    for (int i = t; i < NG*CC; i += 1024) g_pool[i] = 0.0f;
    for (int i = t; i < 13*64; i += 1024) { g_colsum[i] = 0.0f; g_colsq[i] = 0.0f; }
    int lane = t & 31, wid = t >> 5;
    int carry = 0;
    for (int base = 0; base < NN; base += 1024) {
        int i = base + t;
        int v = (i < NN) ? g_cnt[i] : 0;
        int x = v;
        #pragma unroll
        for (int off = 1; off < 32; off <<= 1) {
            int u = __shfl_up_sync(0xffffffffu, x, off);
            if (lane >= off) x += u;
        }
        if (lane == 31) wsum[wid] = x;
        __syncthreads();
        if (wid == 0) {
            int y = wsum[lane];
            #pragma unroll
            for (int off = 1; off < 32; off <<= 1) {
                int u = __shfl_up_sync(0xffffffffu, y, off);
                if (lane >= off) y += u;
            }
            wsum[lane] = y;
        }
        __syncthreads();
        int pre = (wid > 0) ? wsum[wid-1] : 0;
        int excl = carry + pre + x - v;
        if (i < NN) { g_rowptr[i] = excl; g_cursor[i] = excl; }
        int tot = wsum[31];
        __syncthreads();
        carry += tot;
    }
    if (t == 0) g_rowptr[NN] = carry;
}

__global__ void k_scatter(const int* __restrict__ src, const int* __restrict__ dst) {
    int e = blockIdx.x*blockDim.x + threadIdx.x;
    if (e >= NE) return;
    int d = dst[e];
    int p = atomicAdd(&g_cursor[d], 1);
    int2 pk; pk.x = e; pk.y = d;
    g_epack[p] = pk;
    g_csrc[p]  = src[e];
}

// ---------------- edge MLPs: half2, 4 edges/thread (2 per half2 lane), all 13 layers ----------------
__global__ __launch_bounds__(256) void k_edgemlp(
    const float* __restrict__ ea,
    const float* __restrict__ m1W, const float* __restrict__ m1b,
    const float* __restrict__ m2W, const float* __restrict__ m2b,
    const float* __restrict__ hm1W, const float* __restrict__ hm1b,
    const float* __restrict__ hm2W, const float* __restrict__ hm2b)
{
    __shared__ __align__(16) __half2 sw[NL*LSTRIDE];
    // per layer l at sw+l*LSTRIDE (each entry = {w,w}):
    //   [0..255] W1^T (W1T[j*16+i]=W1[i][j]), [256..271] b1, [272..287] W2, [288] b2
    for (int idx = threadIdx.x; idx < NL*LSTRIDE; idx += 256) {
        int l = idx / LSTRIDE, r = idx - l*LSTRIDE;
        float v = 0.0f;
        if (r < 256) {
            int j = r >> 4, i = r & 15;
            v = (l == 0) ? m1W[i*16 + j] : hm1W[(l-1)*256 + i*16 + j];
        } else if (r < 272) {
            v = (l == 0) ? m1b[r-256] : hm1b[(l-1)*16 + (r-256)];
        } else if (r < 288) {
            v = (l == 0) ? m2W[r-272] : hm2W[(l-1)*16 + (r-272)];
        } else if (r == 288) {
            v = (l == 0) ? m2b[0] : hm2b[l-1];
        }
        sw[idx] = __half2half2(__float2half(v));
    }
    __syncthreads();

    int tid = blockIdx.x*256 + threadIdx.x;
    if (tid >= NE/4) return;
    int p0 = tid*4;

    int4 pk01 = *(const int4*)(g_epack + p0);
    int4 pk23 = *(const int4*)(g_epack + p0 + 2);
    int e[4] = {pk01.x, pk01.z, pk23.x, pk23.z};
    int d[4] = {pk01.y, pk01.w, pk23.y, pk23.w};

    // a2[p][i] = {feat_i of edge 2p, feat_i of edge 2p+1}
    __half2 a2[2][16];
    {
        float a[4][16];
        #pragma unroll
        for (int q = 0; q < 4; q++) {
            const float4* ap = (const float4*)(ea + e[q]*16);
            #pragma unroll
            for (int r = 0; r < 4; r++) {
                float4 v = ap[r];
                a[q][4*r+0]=v.x; a[q][4*r+1]=v.y; a[q][4*r+2]=v.z; a[q][4*r+3]=v.w;
            }
        }
        #pragma unroll
        for (int i = 0; i < 16; i++) {
            a2[0][i] = __floats2half2_rn(a[0][i], a[1][i]);
            a2[1][i] = __floats2half2_rn(a[2][i], a[3][i]);
        }
    }

    const __half2 zero2 = __float2half2_rn(0.0f);

    #pragma unroll 1
    for (int l = 0; l < NL; l++) {
        const __half2* W = &sw[l*LSTRIDE];
        __half2 b2v = W[288];
        __half2 z0 = b2v, z1 = b2v;
        #pragma unroll
        for (int j = 0; j < 16; j++) {
            const __half2* wc = &W[j*16];
            __half2 b1j = W[256+j];
            __half2 w2j = W[272+j];
            __half2 t0 = b1j, t1 = b1j;
            #pragma unroll
            for (int i = 0; i < 16; i++) {
                __half2 w = wc[i];
                t0 = __hfma2(a2[0][i], w, t0);
                t1 = __hfma2(a2[1][i], w, t1);
            }
            t0 = __hmax2(t0, zero2);
            t1 = __hmax2(t1, zero2);
            z0 = __hfma2(t0, w2j, z0);
            z1 = __hfma2(t1, w2j, z1);
        }
        float2 f0 = __half22float2(z0);
        float2 f1 = __half22float2(z1);
        float4 ewv;
        ewv.x = 1.0f / (1.0f + __expf(-f0.x));
        ewv.y = 1.0f / (1.0f + __expf(-f0.y));
        ewv.z = 1.0f / (1.0f + __expf(-f1.x));
        ewv.w = 1.0f / (1.0f + __expf(-f1.y));
        *(float4*)(g_ew + l*NE + p0) = ewv;
        atomicAdd(&g_deg[d[0]*16 + l], ewv.x);
        atomicAdd(&g_deg[d[1]*16 + l], ewv.y);
        atomicAdd(&g_deg[d[2]*16 + l], ewv.z);
        atomicAdd(&g_deg[d[3]*16 + l], ewv.w);
    }
}

__global__ void k_rsqrt() {
    int i = blockIdx.x*blockDim.x + threadIdx.x;
    if (i < NN*16) g_deg[i] = rsqrtf(g_deg[i]);   // deg >= 1 always
}

// scale ew by dis_src ONLY (dis_dst factored into k_agg); also re-zero g_cnt
__global__ void k_norm() {
    int p = blockIdx.x*256 + threadIdx.x;   // always < NE
    if (p < NN) g_cnt[p] = 0;               // restore invariant for next replay
    int s = g_csrc[p];
    float ds[16];
    const float4* sp = (const float4*)(g_deg + s*16);
    #pragma unroll
    for (int q = 0; q < 4; q++) {
        float4 v = sp[q]; ds[4*q]=v.x; ds[4*q+1]=v.y; ds[4*q+2]=v.z; ds[4*q+3]=v.w;
    }
    #pragma unroll
    for (int l = 0; l < NL; l++)
        g_ew[l*NE + p] *= ds[l];
}

// ---------------- fused BN+ReLU + tensor-core GEMM (wmma m16n16k16) ----------------
// block = 256 threads (8 warps), 128 rows; each warp: 16 rows x 64 cols
__global__ __launch_bounds__(256) void k_gemm(
    const float* __restrict__ A, const float* __restrict__ W,
    __half* __restrict__ H, int slot)     // slot < 0 : no BN
{
    __shared__ __align__(32) __half sA[128*64];   // 16 KB, fp16 BN-relu'd A tile
    __shared__ __align__(32) __half sW[64*64];    // 8 KB,  fp16 weights (k-major [k][n])
    __shared__ __align__(32) float  sC[8][16*64]; // 32 KB, per-warp fp32 C staging
    __shared__ float smu[64], ssc[64];

    int t = threadIdx.x;
    int base = blockIdx.x*128;

    if (slot >= 0 && t < 64) {
        float mu  = g_colsum[slot*64 + t] * (1.0f/NN);
        float var = g_colsq[slot*64 + t] * (1.0f/NN) - mu*mu;
        if (var < 0.0f) var = 0.0f;
        smu[t] = mu;
        ssc[t] = rsqrtf(var + 1e-5f);
    }
    // weights -> fp16 smem (no dependence on smu)
    {
        const float4* W4 = (const float4*)W;
        for (int i = t; i < 1024; i += 256) {
            float4 v = W4[i];
            __half2 h0 = __floats2half2_rn(v.x, v.y);
            __half2 h1 = __floats2half2_rn(v.z, v.w);
            uint2 u; u.x = *(unsigned*)&h0; u.y = *(unsigned*)&h1;
            *(uint2*)(sW + i*4) = u;
        }
    }
    __syncthreads();   // smu ready for A staging

    // stage A tile: BN+ReLU+fp16 via float4 loads (8 per thread)
    {
        const float4* A4 = (const float4*)A;
        const int maxi = ((NN - base < 128 ? NN - base : 128) * 64) >> 2;  // valid float4s
        for (int i = t; i < 2048; i += 256) {
            float4 v;
            if (i < maxi) v = A4[(size_t)base*16 + i];
            else { v.x = v.y = v.z = v.w = 0.0f; }
            if (slot >= 0) {
                int c = (i & 15)*4;
                v.x = fmaxf((v.x - smu[c+0]) * ssc[c+0], 0.0f);
                v.y = fmaxf((v.y - smu[c+1]) * ssc[c+1], 0.0f);
                v.z = fmaxf((v.z - smu[c+2]) * ssc[c+2], 0.0f);
                v.w = fmaxf((v.w - smu[c+3]) * ssc[c+3], 0.0f);
            }
            __half2 h0 = __floats2half2_rn(v.x, v.y);
            __half2 h1 = __floats2half2_rn(v.z, v.w);
            uint2 u; u.x = *(unsigned*)&h0; u.y = *(unsigned*)&h1;
            *(uint2*)(sA + i*4) = u;
        }
    }
    __syncthreads();

    int w = t >> 5;
    int lane = t & 31;

    wmma::fragment<wmma::accumulator, 16, 16, 16, float> acc[4];
    #pragma unroll
    for (int n = 0; n < 4; n++) wmma::fill_fragment(acc[n], 0.0f);

    #pragma unroll
    for (int k = 0; k < 4; k++) {
        wmma::fragment<wmma::matrix_a, 16, 16, 16, __half, wmma::row_major> af;
        wmma::load_matrix_sync(af, sA + (w*16)*64 + k*16, 64);
        #pragma unroll
        for (int n = 0; n < 4; n++) {
            wmma::fragment<wmma::matrix_b, 16, 16, 16, __half, wmma::row_major> bf;
            wmma::load_matrix_sync(bf, sW + (k*16)*64 + n*16, 64);
            wmma::mma_sync(acc[n], af, bf, acc[n]);
        }
    }

    // stage fp32 -> smem (per-warp private region), then fp16 coalesced store
    #pragma unroll
    for (int n = 0; n < 4; n++)
        wmma::store_matrix_sync(&sC[w][n*16], acc[n], 64, wmma::mem_row_major);

    int wrow = base + w*16;
    if (wrow < NN) {   // NN % 16 == 0, so warp tiles are all-or-nothing
        __half2* H2 = (__half2*)(H + (size_t)wrow*64);
        #pragma unroll
        for (int i = lane; i < 512; i += 32) {
            float x0 = sC[w][2*i], x1 = sC[w][2*i+1];
            H2[i] = __floats2half2_rn(x0, x1);
        }
    }
}

// ---------------- CSR aggregation: LDG.128 gathers + fused epilogues + fused BN stats ----
// lane = (edge slot 0-3)*8 + (col group 0-7); each lane covers 8 fp16 cols.
// weights in nrm are ew*dis_src; self term weight dv (seeded by eg==0 ONLY);
// final result = dv*sum + bias. Grid is EXACTLY NN warps (6250 blocks x 8).
__global__ __launch_bounds__(256) void k_agg(
    const __half* __restrict__ h, const float* __restrict__ nrm,
    int layer, const float* __restrict__ bias,
    float* __restrict__ cur, float* __restrict__ acc,
    const int* __restrict__ batch, int mode, int slot)
{
    __shared__ float bsum[64], bsq[64];
    __shared__ int bcnt;
    int t = threadIdx.x;
    if (mode & M_STATS) {
        if (t < 64) { bsum[t] = 0.0f; bsq[t] = 0.0f; }
        if (t == 0) bcnt = 0;
        __syncthreads();
    }

    int w = (blockIdx.x*256 + t) >> 5;     // < NN always (exact grid)
    int lane = t & 31;
    int eg = lane >> 3;          // edge slot 0..3
    int cg = lane & 7;           // col group 0..7
    int cbase = cg*8;

    float dv = g_deg[w*16 + layer];   // dis_dst

    float a[8] = {0,0,0,0,0,0,0,0};
    if (eg == 0) {   // self term seeded ONCE (reduction sums over the 4 edge slots)
        uint4 hv = *(const uint4*)(h + (size_t)w*64 + cbase);
        const __half2* hh = (const __half2*)&hv;
        #pragma unroll
        for (int i = 0; i < 4; i++) {
            float2 f = __half22float2(hh[i]);
            a[2*i]   = dv * f.x;
            a[2*i+1] = dv * f.y;
        }
    }

    int p0 = g_rowptr[w], p1 = g_rowptr[w+1];
    for (int p = p0; p < p1; p += 4) {
        int ei = p + eg;
        bool valid = (ei < p1);
        int eidx = valid ? ei : p;
        float wt = nrm[eidx];
        if (!valid) wt = 0.0f;
        int s = g_csrc[eidx];
        uint4 hv = *(const uint4*)(h + (size_t)s*64 + cbase);
        const __half2* hh = (const __half2*)&hv;
        #pragma unroll
        for (int i = 0; i < 4; i++) {
            float2 f = __half22float2(hh[i]);
            a[2*i]   = fmaf(wt, f.x, a[2*i]);
            a[2*i+1] = fmaf(wt, f.y, a[2*i+1]);
        }
    }

    // reduce across the 4 edge slots (lanes cg, cg+8, cg+16, cg+24)
    #pragma unroll
    for (int i = 0; i < 8; i++) {
        a[i] += __shfl_xor_sync(0xffffffffu, a[i], 8);
        a[i] += __shfl_xor_sync(0xffffffffu, a[i], 16);
    }

    if (lane < 8) {
        float4 b0 = *(const float4*)(bias + cbase);
        float4 b1 = *(const float4*)(bias + cbase + 4);
        float o[8];
        o[0] = fmaf(dv, a[0], b0.x); o[1] = fmaf(dv, a[1], b0.y);
        o[2] = fmaf(dv, a[2], b0.z); o[3] = fmaf(dv, a[3], b0.w);
        o[4] = fmaf(dv, a[4], b1.x); o[5] = fmaf(dv, a[5], b1.y);
        o[6] = fmaf(dv, a[6], b1.z); o[7] = fmaf(dv, a[7], b1.w);

        size_t off = (size_t)w*64 + cbase;
        if (mode & M_SKIP) {
            float4 s0 = *(float4*)(acc + off);
            float4 s1 = *(float4*)(acc + off + 4);
            o[0] += s0.x; o[1] += s0.y; o[2] += s0.z; o[3] += s0.w;
            o[4] += s1.x; o[5] += s1.y; o[6] += s1.z; o[7] += s1.w;
            s0.x += o[0]; s0.y += o[1]; s0.z += o[2]; s0.w += o[3];
            s1.x += o[4]; s1.y += o[5]; s1.z += o[6]; s1.w += o[7];
            *(float4*)(acc + off)     = s0;
            *(float4*)(acc + off + 4) = s1;
        }
        float4 c0, c1;
        c0.x=o[0]; c0.y=o[1]; c0.z=o[2]; c0.w=o[3];
        c1.x=o[4]; c1.y=o[5]; c1.z=o[6]; c1.w=o[7];
        *(float4*)(cur + off)     = c0;
        *(float4*)(cur + off + 4) = c1;
        if (mode & M_COPY) {
            *(float4*)(acc + off)     = c0;
            *(float4*)(acc + off + 4) = c1;
        }
        if (mode & M_POOL) {
            int b = batch[w];
            #pragma unroll
            for (int i = 0; i < 8; i++) {
                float rv = fmaxf(o[i], 0.0f);
                atomicMax((int*)&g_pool[b*64 + cbase + i], __float_as_int(rv));
            }
        }
        if (mode & M_STATS) {
            #pragma unroll
            for (int i = 0; i < 8; i++) {
                atomicAdd(&bsum[cbase + i], o[i]);
                atomicAdd(&bsq [cbase + i], o[i]*o[i]);
            }
        }
    }

    if (mode & M_STATS) {
        __syncwarp();
        __threadfence_block();
        int old = 0;
        if (lane == 0) old = atomicAdd(&bcnt, 1);
        old = __shfl_sync(0xffffffffu, old, 0);
        if (old == 7) {            // last warp of the block flushes
            __threadfence_block();
            #pragma unroll
            for (int i = 0; i < 2; i++) {
                int c = lane + i*32;
                atomicAdd(&g_colsum[slot*64 + c], bsum[c]);
                atomicAdd(&g_colsq [slot*64 + c], bsq[c]);
            }
        }
    }
}

// ---------------- readout ----------------
__global__ void k_final(const float* __restrict__ linW, const float* __restrict__ linb,
                        float* __restrict__ out) {
    int g = blockIdx.x*blockDim.x + threadIdx.x;
    if (g >= NG) return;
    float a0 = linb[0], a1 = linb[1];
    #pragma unroll 8
    for (int c = 0; c < CC; c++) {
        float v = g_pool[g*64 + c];
        a0 = fmaf(v, linW[c*2+0], a0);
        a1 = fmaf(v, linW[c*2+1], a1);
    }
    out[g*2+0] = a0;
    out[g*2+1] = a1;
}

// ---------------- launch ----------------
extern "C" void kernel_launch(void* const* d_in, const int* in_sizes, int n_in,
                              void* d_out, int out_size)
{
    const float* x     = (const float*)d_in[0];
    const int*   ei    = (const int*)  d_in[1];
    const int*   batch = (const int*)  d_in[2];
    /* d_in[3] = dropout (unused, eval mode) */
    const float* ea    = (const float*)d_in[4];
    const float* Wlin1 = (const float*)d_in[5];
    const float* bias1 = (const float*)d_in[6];
    const float* m1W1  = (const float*)d_in[7];
    const float* m1b1  = (const float*)d_in[8];
    const float* m2W1  = (const float*)d_in[9];
    const float* m2b1  = (const float*)d_in[10];
    const float* hWlin = (const float*)d_in[11];
    const float* hbias = (const float*)d_in[12];
    const float* hm1W  = (const float*)d_in[13];
    const float* hm1b  = (const float*)d_in[14];
    const float* hm2W  = (const float*)d_in[15];
    const float* hm2b  = (const float*)d_in[16];
    const float* linW  = (const float*)d_in[17];
    const float* linb  = (const float*)d_in[18];
    float* out = (float*)d_out;

    const int* src = ei;
    const int* dst = ei + NE;

    __half *p_h;
    float *p_cur, *p_acc, *p_ew;
    cudaGetSymbolAddress((void**)&p_h,   g_h);
    cudaGetSymbolAddress((void**)&p_cur, g_cur);
    cudaGetSymbolAddress((void**)&p_acc, g_acc);
    cudaGetSymbolAddress((void**)&p_ew,  g_ew);

    const int EB = NE / 256;                  // 3125 (exact)
    const int MB = (NE/4 + 255) / 256;        // 782 (edgemlp, 4 edges/thread)
    const int GB = (NN + 127) / 128;          // 391 (gemm, 128 rows/block)
    const int AB = (NN*32) / 256;             // 6250 (exact -> 50000 warps = NN)

    // prologue: CSR + all edge norms for all 13 layers
    k_hist   <<<EB, 256>>>(dst);              // also inits g_deg=1.0
    k_scanall<<<1, 1024>>>();                 // also zeroes pool + BN stats
    k_scatter<<<EB, 256>>>(src, dst);
    k_edgemlp<<<MB, 256>>>(ea, m1W1, m1b1, m2W1, m2b1, hm1W, hm1b, hm2W, hm2b);
    k_rsqrt  <<<EB, 256>>>();
    k_norm   <<<EB, 256>>>();                 // also re-zeroes g_cnt

    // conv1: gemm (no BN), agg writes stats slot 0 (consumed by hidden gemm 0)
    k_gemm<<<GB, 256>>>(x, Wlin1, p_h, -1);
    k_agg <<<AB, 256>>>(p_h, p_ew, 0, bias1, p_cur, p_acc, batch, M_COPY | M_STATS, 0);

    // 12 hidden convs (6 blocks x 2)
    for (int j = 0; j < 12; j++) {
        int l = j + 1;
        k_gemm<<<GB, 256>>>(p_cur, hWlin + j*CC*CC, p_h, j);
        int mode;
        if (j == 11)      mode = M_SKIP | M_POOL;             // last: skip + relu + pool
        else if (j & 1)   mode = M_SKIP | M_STATS;            // end of block: dense skip
        else              mode = M_STATS;
        k_agg <<<AB, 256>>>(p_h, p_ew + l*NE, l, hbias + j*CC, p_cur, p_acc, batch, mode, l);
    }

    k_final<<<(NG + 63)/64, 64>>>(linW, linb, out);
}

// round 13
// speedup vs baseline: 1.0978x; 1.0978x over previous
#include <cuda_runtime.h>
#include <cuda_fp16.h>
#include <mma.h>
#include <math.h>

using namespace nvcuda;

#define NN 50000
#define NE 800000
#define NG 500
#define CC 64
#define NL 13          // 1 + 12 PDN convs
#define LSTRIDE 292    // per-layer smem stride (half2 entries) for edge MLP weights

// modes for k_agg epilogue
#define M_COPY  1
#define M_SKIP  2
#define M_POOL  8

// ---------------- scratch (device globals; no allocation) ----------------
__device__ __half g_h  [NN*CC];     // fp16 GEMM output (gather bandwidth halved)
__device__ float  g_cur[NN*CC];
__device__ float  g_acc[NN*CC];
__device__ float  g_ew [NL*NE];     // raw ew (CSR order) -> scaled to ew*dis_src in k_norm
__device__ float  g_deg[NN*16];     // [node][16] deg -> rsqrt(deg) in place (k_rsqrt)
__device__ int    g_cnt[NN];        // zero at entry (static init / re-zeroed by k_norm)
__device__ int    g_rowptr[NN+1];
__device__ int    g_cursor[NN];
__device__ __align__(16) int2 g_epack[NE];   // {eid, dst} in CSR order
__device__ int    g_csrc[NE];
__device__ float  g_colsum[13*64];  // fp32 BN stats (zeroed in k_scanall)
__device__ float  g_colsq [13*64];
__device__ float  g_pool[NG*CC];    // zeroed in k_scanall

// ---------------- CSR build ----------------
// NE == 3125*256 exactly; also NE == NN*16, so this thread grid covers g_deg init.
__global__ void k_hist(const int* __restrict__ dst) {
    int e = blockIdx.x*blockDim.x + threadIdx.x;
    g_deg[e] = 1.0f;                 // deg starts at self-loop weight 1
    atomicAdd(&g_cnt[dst[e]], 1);    // g_cnt zero at entry
}

// single-block chunked scan: 1024 threads, 49 chunks; also zeroes pool/stats
__global__ void k_scanall() {
    __shared__ int wsum[32];
    int t = threadIdx.x;
    for (int i = t; i < NG*CC; i += 1024) g_pool[i] = 0.0f;
    for (int i = t; i < 13*64; i += 1024) { g_colsum[i] = 0.0f; g_colsq[i] = 0.0f; }
    int lane = t & 31, wid = t >> 5;
    int carry = 0;
    for (int base = 0; base < NN; base += 1024) {
        int i = base + t;
        int v = (i < NN) ? g_cnt[i] : 0;
        int x = v;
        #pragma unroll
        for (int off = 1; off < 32; off <<= 1) {
            int u = __shfl_up_sync(0xffffffffu, x, off);
            if (lane >= off) x += u;
        }
        if (lane == 31) wsum[wid] = x;
        __syncthreads();
        if (wid == 0) {
            int y = wsum[lane];
            #pragma unroll
            for (int off = 1; off < 32; off <<= 1) {
                int u = __shfl_up_sync(0xffffffffu, y, off);
                if (lane >= off) y += u;
            }
            wsum[lane] = y;
        }
        __syncthreads();
        int pre = (wid > 0) ? wsum[wid-1] : 0;
        int excl = carry + pre + x - v;
        if (i < NN) { g_rowptr[i] = excl; g_cursor[i] = excl; }
        int tot = wsum[31];
        __syncthreads();
        carry += tot;
    }
    if (t == 0) g_rowptr[NN] = carry;
}

__global__ void k_scatter(const int* __restrict__ src, const int* __restrict__ dst) {
    int e = blockIdx.x*blockDim.x + threadIdx.x;
    if (e >= NE) return;
    int d = dst[e];
    int p = atomicAdd(&g_cursor[d], 1);
    int2 pk; pk.x = e; pk.y = d;
    g_epack[p] = pk;
    g_csrc[p]  = src[e];
}

// ---------------- edge MLPs: half2, 4 edges/thread, LDS.128 weight loads ----------------
__global__ __launch_bounds__(256) void k_edgemlp(
    const float* __restrict__ ea,
    const float* __restrict__ m1W, const float* __restrict__ m1b,
    const float* __restrict__ m2W, const float* __restrict__ m2b,
    const float* __restrict__ hm1W, const float* __restrict__ hm1b,
    const float* __restrict__ hm2W, const float* __restrict__ hm2b)
{
    __shared__ __align__(16) __half2 sw[NL*LSTRIDE];
    // per layer l at sw+l*LSTRIDE (each entry = {w,w}):
    //   [0..255] W1^T (W1T[j*16+i]=W1[i][j]), [256..271] b1, [272..287] W2, [288] b2
    for (int idx = threadIdx.x; idx < NL*LSTRIDE; idx += 256) {
        int l = idx / LSTRIDE, r = idx - l*LSTRIDE;
        float v = 0.0f;
        if (r < 256) {
            int j = r >> 4, i = r & 15;
            v = (l == 0) ? m1W[i*16 + j] : hm1W[(l-1)*256 + i*16 + j];
        } else if (r < 272) {
            v = (l == 0) ? m1b[r-256] : hm1b[(l-1)*16 + (r-256)];
        } else if (r < 288) {
            v = (l == 0) ? m2W[r-272] : hm2W[(l-1)*16 + (r-272)];
        } else if (r == 288) {
            v = (l == 0) ? m2b[0] : hm2b[l-1];
        }
        sw[idx] = __half2half2(__float2half(v));
    }
    __syncthreads();

    int tid = blockIdx.x*256 + threadIdx.x;
    if (tid >= NE/4) return;
    int p0 = tid*4;

    int4 pk01 = *(const int4*)(g_epack + p0);
    int4 pk23 = *(const int4*)(g_epack + p0 + 2);
    int e[4] = {pk01.x, pk01.z, pk23.x, pk23.z};
    int d[4] = {pk01.y, pk01.w, pk23.y, pk23.w};

    // a2[p][i] = {feat_i of edge 2p, feat_i of edge 2p+1}
    __half2 a2[2][16];
    {
        float a[4][16];
        #pragma unroll
        for (int q = 0; q < 4; q++) {
            const float4* ap = (const float4*)(ea + e[q]*16);
            #pragma unroll
            for (int r = 0; r < 4; r++) {
                float4 v = ap[r];
                a[q][4*r+0]=v.x; a[q][4*r+1]=v.y; a[q][4*r+2]=v.z; a[q][4*r+3]=v.w;
            }
        }
        #pragma unroll
        for (int i = 0; i < 16; i++) {
            a2[0][i] = __floats2half2_rn(a[0][i], a[1][i]);
            a2[1][i] = __floats2half2_rn(a[2][i], a[3][i]);
        }
    }

    const __half2 zero2 = __float2half2_rn(0.0f);

    #pragma unroll 1
    for (int l = 0; l < NL; l++) {
        const __half2* W = &sw[l*LSTRIDE];
        __half2 b2v = W[288];
        __half2 z0 = b2v, z1 = b2v;
        #pragma unroll
        for (int j = 0; j < 16; j++) {
            const uint4* wc4 = (const uint4*)&W[j*16];   // 4x LDS.128 = 16 half2 weights
            __half2 b1j = W[256+j];
            __half2 w2j = W[272+j];
            __half2 t0 = b1j, t1 = b1j;
            #pragma unroll
            for (int i4 = 0; i4 < 4; i4++) {
                uint4 u = wc4[i4];
                __half2 w0 = *(__half2*)&u.x;
                __half2 w1 = *(__half2*)&u.y;
                __half2 w2 = *(__half2*)&u.z;
                __half2 w3 = *(__half2*)&u.w;
                t0 = __hfma2(a2[0][i4*4+0], w0, t0); t1 = __hfma2(a2[1][i4*4+0], w0, t1);
                t0 = __hfma2(a2[0][i4*4+1], w1, t0); t1 = __hfma2(a2[1][i4*4+1], w1, t1);
                t0 = __hfma2(a2[0][i4*4+2], w2, t0); t1 = __hfma2(a2[1][i4*4+2], w2, t1);
                t0 = __hfma2(a2[0][i4*4+3], w3, t0); t1 = __hfma2(a2[1][i4*4+3], w3, t1);
            }
            t0 = __hmax2(t0, zero2);
            t1 = __hmax2(t1, zero2);
            z0 = __hfma2(t0, w2j, z0);
            z1 = __hfma2(t1, w2j, z1);
        }
        float2 f0 = __half22float2(z0);
        float2 f1 = __half22float2(z1);
        float4 ewv;
        ewv.x = 1.0f / (1.0f + __expf(-f0.x));
        ewv.y = 1.0f / (1.0f + __expf(-f0.y));
        ewv.z = 1.0f / (1.0f + __expf(-f1.x));
        ewv.w = 1.0f / (1.0f + __expf(-f1.y));
        *(float4*)(g_ew + l*NE + p0) = ewv;
        atomicAdd(&g_deg[d[0]*16 + l], ewv.x);
        atomicAdd(&g_deg[d[1]*16 + l], ewv.y);
        atomicAdd(&g_deg[d[2]*16 + l], ewv.z);
        atomicAdd(&g_deg[d[3]*16 + l], ewv.w);
    }
}

__global__ void k_rsqrt() {
    int i = blockIdx.x*blockDim.x + threadIdx.x;
    if (i < NN*16) g_deg[i] = rsqrtf(g_deg[i]);   // deg >= 1 always
}

// scale ew by dis_src ONLY (dis_dst factored into k_agg); also re-zero g_cnt
__global__ void k_norm() {
    int p = blockIdx.x*256 + threadIdx.x;   // always < NE
    if (p < NN) g_cnt[p] = 0;               // restore invariant for next replay
    int s = g_csrc[p];
    float ds[16];
    const float4* sp = (const float4*)(g_deg + s*16);
    #pragma unroll
    for (int q = 0; q < 4; q++) {
        float4 v = sp[q]; ds[4*q]=v.x; ds[4*q+1]=v.y; ds[4*q+2]=v.z; ds[4*q+3]=v.w;
    }
    #pragma unroll
    for (int l = 0; l < NL; l++)
        g_ew[l*NE + p] *= ds[l];
}

// ---------------- fused BN+ReLU + tensor-core GEMM (wmma m16n16k16) ----------------
// block = 256 threads (8 warps), 128 rows; each warp: 16 rows x 64 cols
__global__ __launch_bounds__(256) void k_gemm(
    const float* __restrict__ A, const float* __restrict__ W,
    __half* __restrict__ H, int slot)     // slot < 0 : no BN
{
    __shared__ __align__(32) __half sA[128*64];   // 16 KB, fp16 BN-relu'd A tile
    __shared__ __align__(32) __half sW[64*64];    // 8 KB,  fp16 weights (k-major [k][n])
    __shared__ __align__(32) float  sC[8][16*64]; // 32 KB, per-warp fp32 C staging
    __shared__ float smu[64], ssc[64];

    int t = threadIdx.x;
    int base = blockIdx.x*128;

    if (slot >= 0 && t < 64) {
        float mu  = g_colsum[slot*64 + t] * (1.0f/NN);
        float var = g_colsq[slot*64 + t] * (1.0f/NN) - mu*mu;
        if (var < 0.0f) var = 0.0f;
        smu[t] = mu;
        ssc[t] = rsqrtf(var + 1e-5f);
    }
    // weights -> fp16 smem (no dependence on smu)
    {
        const float4* W4 = (const float4*)W;
        for (int i = t; i < 1024; i += 256) {
            float4 v = W4[i];
            __half2 h0 = __floats2half2_rn(v.x, v.y);
            __half2 h1 = __floats2half2_rn(v.z, v.w);
            uint2 u; u.x = *(unsigned*)&h0; u.y = *(unsigned*)&h1;
            *(uint2*)(sW + i*4) = u;
        }
    }
    __syncthreads();   // smu ready for A staging

    // stage A tile: BN+ReLU+fp16 via float4 loads (8 per thread)
    {
        const float4* A4 = (const float4*)A;
        const int maxi = ((NN - base < 128 ? NN - base : 128) * 64) >> 2;  // valid float4s
        for (int i = t; i < 2048; i += 256) {
            float4 v;
            if (i < maxi) v = A4[(size_t)base*16 + i];
            else { v.x = v.y = v.z = v.w = 0.0f; }
            if (slot >= 0) {
                int c = (i & 15)*4;
                v.x = fmaxf((v.x - smu[c+0]) * ssc[c+0], 0.0f);
                v.y = fmaxf((v.y - smu[c+1]) * ssc[c+1], 0.0f);
                v.z = fmaxf((v.z - smu[c+2]) * ssc[c+2], 0.0f);
                v.w = fmaxf((v.w - smu[c+3]) * ssc[c+3], 0.0f);
            }
            __half2 h0 = __floats2half2_rn(v.x, v.y);
            __half2 h1 = __floats2half2_rn(v.z, v.w);
            uint2 u; u.x = *(unsigned*)&h0; u.y = *(unsigned*)&h1;
            *(uint2*)(sA + i*4) = u;
        }
    }
    __syncthreads();

    int w = t >> 5;
    int lane = t & 31;

    wmma::fragment<wmma::accumulator, 16, 16, 16, float> acc[4];
    #pragma unroll
    for (int n = 0; n < 4; n++) wmma::fill_fragment(acc[n], 0.0f);

    #pragma unroll
    for (int k = 0; k < 4; k++) {
        wmma::fragment<wmma::matrix_a, 16, 16, 16, __half, wmma::row_major> af;
        wmma::load_matrix_sync(af, sA + (w*16)*64 + k*16, 64);
        #pragma unroll
        for (int n = 0; n < 4; n++) {
            wmma::fragment<wmma::matrix_b, 16, 16, 16, __half, wmma::row_major> bf;
            wmma::load_matrix_sync(bf, sW + (k*16)*64 + n*16, 64);
            wmma::mma_sync(acc[n], af, bf, acc[n]);
        }
    }

    // stage fp32 -> smem (per-warp private region), then fp16 coalesced store
    #pragma unroll
    for (int n = 0; n < 4; n++)
        wmma::store_matrix_sync(&sC[w][n*16], acc[n], 64, wmma::mem_row_major);

    int wrow = base + w*16;
    if (wrow < NN) {   // NN % 16 == 0, so warp tiles are all-or-nothing
        __half2* H2 = (__half2*)(H + (size_t)wrow*64);
        #pragma unroll
        for (int i = lane; i < 512; i += 32) {
            float x0 = sC[w][2*i], x1 = sC[w][2*i+1];
            H2[i] = __floats2half2_rn(x0, x1);
        }
    }
}

// ---------------- BN statistics (standalone; fp32 partials -> float atomics) ----------------
__global__ void k_bnstats(const float* __restrict__ A, int slot) {
    int t = threadIdx.x;
    int c = t & 63, rg = t >> 6;              // 256 threads: 4 row lanes x 64 cols
    float s = 0.0f, q = 0.0f;                 // ~49 elements per thread: fp32 is exact enough
    for (int r = blockIdx.x*4 + rg; r < NN; r += gridDim.x*4) {
        float v = A[r*64 + c];
        s += v; q = fmaf(v, v, q);
    }
    __shared__ float ss[256], sq[256];
    ss[t] = s; sq[t] = q; __syncthreads();
    if (t < 64) {
        float S = ss[t] + ss[t+64] + ss[t+128] + ss[t+192];
        float Q = sq[t] + sq[t+64] + sq[t+128] + sq[t+192];
        atomicAdd(&g_colsum[slot*64 + c], S);
        atomicAdd(&g_colsq [slot*64 + c], Q);
    }
}

// ---------------- CSR aggregation: LDG.128 gathers + fused elementwise epilogues ----------
// lane = (edge slot 0-3)*8 + (col group 0-7); each lane covers 8 fp16 cols.
// weights in nrm are ew*dis_src; self term weight dv (seeded by eg==0 ONLY);
// final result = dv*sum + bias.
__global__ __launch_bounds__(256) void k_agg(
    const __half* __restrict__ h, const float* __restrict__ nrm,
    int layer, const float* __restrict__ bias,
    float* __restrict__ cur, float* __restrict__ acc,
    const int* __restrict__ batch, int mode)
{
    int t = threadIdx.x;
    int w = (blockIdx.x*256 + t) >> 5;     // < NN always (exact grid)
    int lane = t & 31;
    int eg = lane >> 3;          // edge slot 0..3
    int cg = lane & 7;           // col group 0..7
    int cbase = cg*8;

    float dv = g_deg[w*16 + layer];   // dis_dst

    float a[8] = {0,0,0,0,0,0,0,0};
    if (eg == 0) {   // self term seeded ONCE (reduction sums over the 4 edge slots)
        uint4 hv = *(const uint4*)(h + (size_t)w*64 + cbase);
        const __half2* hh = (const __half2*)&hv;
        #pragma unroll
        for (int i = 0; i < 4; i++) {
            float2 f = __half22float2(hh[i]);
            a[2*i]   = dv * f.x;
            a[2*i+1] = dv * f.y;
        }
    }

    int p0 = g_rowptr[w], p1 = g_rowptr[w+1];
    for (int p = p0; p < p1; p += 4) {
        int ei = p + eg;
        bool valid = (ei < p1);
        int eidx = valid ? ei : p;
        float wt = nrm[eidx];
        if (!valid) wt = 0.0f;
        int s = g_csrc[eidx];
        uint4 hv = *(const uint4*)(h + (size_t)s*64 + cbase);
        const __half2* hh = (const __half2*)&hv;
        #pragma unroll
        for (int i = 0; i < 4; i++) {
            float2 f = __half22float2(hh[i]);
            a[2*i]   = fmaf(wt, f.x, a[2*i]);
            a[2*i+1] = fmaf(wt, f.y, a[2*i+1]);
        }
    }

    // reduce across the 4 edge slots (lanes cg, cg+8, cg+16, cg+24)
    #pragma unroll
    for (int i = 0; i < 8; i++) {
        a[i] += __shfl_xor_sync(0xffffffffu, a[i], 8);
        a[i] += __shfl_xor_sync(0xffffffffu, a[i], 16);
    }

    if (lane < 8) {
        float4 b0 = *(const float4*)(bias + cbase);
        float4 b1 = *(const float4*)(bias + cbase + 4);
        float o[8];
        o[0] = fmaf(dv, a[0], b0.x); o[1] = fmaf(dv, a[1], b0.y);
        o[2] = fmaf(dv, a[2], b0.z); o[3] = fmaf(dv, a[3], b0.w);
        o[4] = fmaf(dv, a[4], b1.x); o[5] = fmaf(dv, a[5], b1.y);
        o[6] = fmaf(dv, a[6], b1.z); o[7] = fmaf(dv, a[7], b1.w);

        size_t off = (size_t)w*64 + cbase;
        if (mode & M_SKIP) {
            float4 s0 = *(float4*)(acc + off);
            float4 s1 = *(float4*)(acc + off + 4);
            o[0] += s0.x; o[1] += s0.y; o[2] += s0.z; o[3] += s0.w;
            o[4] += s1.x; o[5] += s1.y; o[6] += s1.z; o[7] += s1.w;
            s0.x += o[0]; s0.y += o[1]; s0.z += o[2]; s0.w += o[3];
            s1.x += o[4]; s1.y += o[5]; s1.z += o[6]; s1.w += o[7];
            *(float4*)(acc + off)     = s0;
            *(float4*)(acc + off + 4) = s1;
        }
        float4 c0, c1;
        c0.x=o[0]; c0.y=o[1]; c0.z=o[2]; c0.w=o[3];
        c1.x=o[4]; c1.y=o[5]; c1.z=o[6]; c1.w=o[7];
        *(float4*)(cur + off)     = c0;
        *(float4*)(cur + off + 4) = c1;
        if (mode & M_COPY) {
            *(float4*)(acc + off)     = c0;
            *(float4*)(acc + off + 4) = c1;
        }
        if (mode & M_POOL) {
            int b = batch[w];
            #pragma unroll
            for (int i = 0; i < 8; i++) {
                float rv = fmaxf(o[i], 0.0f);
                atomicMax((int*)&g_pool[b*64 + cbase + i], __float_as_int(rv));
            }
        }
    }
}

// ---------------- readout ----------------
__global__ void k_final(const float* __restrict__ linW, const float* __restrict__ linb,
                        float* __restrict__ out) {
    int g = blockIdx.x*blockDim.x + threadIdx.x;
    if (g >= NG) return;
    float a0 = linb[0], a1 = linb[1];
    #pragma unroll 8
    for (int c = 0; c < CC; c++) {
        float v = g_pool[g*64 + c];
        a0 = fmaf(v, linW[c*2+0], a0);
        a1 = fmaf(v, linW[c*2+1], a1);
    }
    out[g*2+0] = a0;
    out[g*2+1] = a1;
}

// ---------------- launch ----------------
extern "C" void kernel_launch(void* const* d_in, const int* in_sizes, int n_in,
                              void* d_out, int out_size)
{
    const float* x     = (const float*)d_in[0];
    const int*   ei    = (const int*)  d_in[1];
    const int*   batch = (const int*)  d_in[2];
    /* d_in[3] = dropout (unused, eval mode) */
    const float* ea    = (const float*)d_in[4];
    const float* Wlin1 = (const float*)d_in[5];
    const float* bias1 = (const float*)d_in[6];
    const float* m1W1  = (const float*)d_in[7];
    const float* m1b1  = (const float*)d_in[8];
    const float* m2W1  = (const float*)d_in[9];
    const float* m2b1  = (const float*)d_in[10];
    const float* hWlin = (const float*)d_in[11];
    const float* hbias = (const float*)d_in[12];
    const float* hm1W  = (const float*)d_in[13];
    const float* hm1b  = (const float*)d_in[14];
    const float* hm2W  = (const float*)d_in[15];
    const float* hm2b  = (const float*)d_in[16];
    const float* linW  = (const float*)d_in[17];
    const float* linb  = (const float*)d_in[18];
    float* out = (float*)d_out;

    const int* src = ei;
    const int* dst = ei + NE;

    __half *p_h;
    float *p_cur, *p_acc, *p_ew;
    cudaGetSymbolAddress((void**)&p_h,   g_h);
    cudaGetSymbolAddress((void**)&p_cur, g_cur);
    cudaGetSymbolAddress((void**)&p_acc, g_acc);
    cudaGetSymbolAddress((void**)&p_ew,  g_ew);

    const int EB = NE / 256;                  // 3125 (exact)
    const int MB = (NE/4 + 255) / 256;        // 782 (edgemlp, 4 edges/thread)
    const int GB = (NN + 127) / 128;          // 391 (gemm, 128 rows/block)
    const int AB = (NN*32) / 256;             // 6250 (exact -> 50000 warps = NN)

    // prologue: CSR + all edge norms for all 13 layers
    k_hist   <<<EB, 256>>>(dst);              // also inits g_deg=1.0
    k_scanall<<<1, 1024>>>();                 // also zeroes pool + BN stats
    k_scatter<<<EB, 256>>>(src, dst);
    k_edgemlp<<<MB, 256>>>(ea, m1W1, m1b1, m2W1, m2b1, hm1W, hm1b, hm2W, hm2b);
    k_rsqrt  <<<EB, 256>>>();
    k_norm   <<<EB, 256>>>();                 // also re-zeroes g_cnt

    // conv1
    k_gemm<<<GB, 256>>>(x, Wlin1, p_h, -1);
    k_agg <<<AB, 256>>>(p_h, p_ew, 0, bias1, p_cur, p_acc, batch, M_COPY);

    // 12 hidden convs (6 blocks x 2)
    for (int j = 0; j < 12; j++) {
        int l = j + 1;
        k_bnstats<<<256, 256>>>(p_cur, j);
        k_gemm<<<GB, 256>>>(p_cur, hWlin + j*CC*CC, p_h, j);
        int mode;
        if (j == 11)      mode = M_SKIP | M_POOL;   // last: skip + relu + pool
        else if (j & 1)   mode = M_SKIP;            // end of block: dense skip
        else              mode = 0;
        k_agg <<<AB, 256>>>(p_h, p_ew + l*NE, l, hbias + j*CC, p_cur, p_acc, batch, mode);
    }

    k_final<<<(NG + 63)/64, 64>>>(linW, linb, out);
}

// round 14
// speedup vs baseline: 1.1099x; 1.0110x over previous
#include <cuda_runtime.h>
#include <cuda_fp16.h>
#include <mma.h>
#include <math.h>

using namespace nvcuda;

#define NN 50000
#define NE 800000
#define NG 500
#define CC 64
#define NL 13          // 1 + 12 PDN convs
#define LSTRIDE 292    // per-layer smem stride (half2 entries) for edge MLP weights

// modes for k_agg epilogue
#define M_COPY  1
#define M_SKIP  2
#define M_POOL  8

// ---------------- scratch (device globals; no allocation) ----------------
__device__ __half g_h  [NN*CC];     // fp16 GEMM output (gather bandwidth halved)
__device__ float  g_cur[NN*CC];
__device__ float  g_acc[NN*CC];
__device__ float  g_ew [NL*NE];     // raw ew (CSR order) -> scaled to ew*dis_src in k_norm
__device__ float  g_deg[NN*16];     // [node][16] degree (raw; rsqrt applied at use sites)
__device__ int    g_cnt[NN];        // zero at entry (static init / re-zeroed by k_norm)
__device__ int    g_rowptr[NN+1];
__device__ int    g_cursor[NN];
__device__ __align__(16) int2 g_epack[NE];   // {eid, dst} in CSR order
__device__ int    g_csrc[NE];
__device__ float  g_colsum[13*64];  // fp32 BN stats (zeroed in k_scanall)
__device__ float  g_colsq [13*64];
__device__ float  g_pool[NG*CC];    // zeroed in k_scanall

// ---------------- CSR build ----------------
// NE == 3125*256 exactly; also NE == NN*16, so this thread grid covers g_deg init.
__global__ void k_hist(const int* __restrict__ dst) {
    int e = blockIdx.x*blockDim.x + threadIdx.x;
    g_deg[e] = 1.0f;                 // deg starts at self-loop weight 1
    atomicAdd(&g_cnt[dst[e]], 1);    // g_cnt zero at entry
}

// single-block chunked scan: 1024 threads, 49 chunks; also zeroes pool/stats
__global__ void k_scanall() {
    __shared__ int wsum[32];
    int t = threadIdx.x;
    for (int i = t; i < NG*CC; i += 1024) g_pool[i] = 0.0f;
    for (int i = t; i < 13*64; i += 1024) { g_colsum[i] = 0.0f; g_colsq[i] = 0.0f; }
    int lane = t & 31, wid = t >> 5;
    int carry = 0;
    for (int base = 0; base < NN; base += 1024) {
        int i = base + t;
        int v = (i < NN) ? g_cnt[i] : 0;
        int x = v;
        #pragma unroll
        for (int off = 1; off < 32; off <<= 1) {
            int u = __shfl_up_sync(0xffffffffu, x, off);
            if (lane >= off) x += u;
        }
        if (lane == 31) wsum[wid] = x;
        __syncthreads();
        if (wid == 0) {
            int y = wsum[lane];
            #pragma unroll
            for (int off = 1; off < 32; off <<= 1) {
                int u = __shfl_up_sync(0xffffffffu, y, off);
                if (lane >= off) y += u;
            }
            wsum[lane] = y;
        }
        __syncthreads();
        int pre = (wid > 0) ? wsum[wid-1] : 0;
        int excl = carry + pre + x - v;
        if (i < NN) { g_rowptr[i] = excl; g_cursor[i] = excl; }
        int tot = wsum[31];
        __syncthreads();
        carry += tot;
    }
    if (t == 0) g_rowptr[NN] = carry;
}

__global__ void k_scatter(const int* __restrict__ src, const int* __restrict__ dst) {
    int e = blockIdx.x*blockDim.x + threadIdx.x;
    if (e >= NE) return;
    int d = dst[e];
    int p = atomicAdd(&g_cursor[d], 1);
    int2 pk; pk.x = e; pk.y = d;
    g_epack[p] = pk;
    g_csrc[p]  = src[e];
}

// ---------------- edge MLPs: half2, 2 edges/thread, 2 hidden units in flight ----------------
__global__ __launch_bounds__(256) void k_edgemlp(
    const float* __restrict__ ea,
    const float* __restrict__ m1W, const float* __restrict__ m1b,
    const float* __restrict__ m2W, const float* __restrict__ m2b,
    const float* __restrict__ hm1W, const float* __restrict__ hm1b,
    const float* __restrict__ hm2W, const float* __restrict__ hm2b)
{
    __shared__ __align__(16) __half2 sw[NL*LSTRIDE];
    // per layer l at sw+l*LSTRIDE (each entry = {w,w}):
    //   [0..255] W1^T (W1T[j*16+i]=W1[i][j]), [256..271] b1, [272..287] W2, [288] b2
    for (int idx = threadIdx.x; idx < NL*LSTRIDE; idx += 256) {
        int l = idx / LSTRIDE, r = idx - l*LSTRIDE;
        float v = 0.0f;
        if (r < 256) {
            int j = r >> 4, i = r & 15;
            v = (l == 0) ? m1W[i*16 + j] : hm1W[(l-1)*256 + i*16 + j];
        } else if (r < 272) {
            v = (l == 0) ? m1b[r-256] : hm1b[(l-1)*16 + (r-256)];
        } else if (r < 288) {
            v = (l == 0) ? m2W[r-272] : hm2W[(l-1)*16 + (r-272)];
        } else if (r == 288) {
            v = (l == 0) ? m2b[0] : hm2b[l-1];
        }
        sw[idx] = __half2half2(__float2half(v));
    }
    __syncthreads();

    int tid = blockIdx.x*256 + threadIdx.x;
    if (tid >= NE/2) return;
    int p0 = tid*2;

    int4 pk = *(const int4*)(g_epack + p0);   // 2 edges: {e0,d0,e1,d1}
    int e0 = pk.x, d0 = pk.y, e1 = pk.z, d1 = pk.w;

    // a2[i] = {feat_i of edge0, feat_i of edge1}
    __half2 a2[16];
    {
        float a0v[16], a1v[16];
        const float4* ap0 = (const float4*)(ea + e0*16);
        const float4* ap1 = (const float4*)(ea + e1*16);
        #pragma unroll
        for (int r = 0; r < 4; r++) {
            float4 v0 = ap0[r], v1 = ap1[r];
            a0v[4*r+0]=v0.x; a0v[4*r+1]=v0.y; a0v[4*r+2]=v0.z; a0v[4*r+3]=v0.w;
            a1v[4*r+0]=v1.x; a1v[4*r+1]=v1.y; a1v[4*r+2]=v1.z; a1v[4*r+3]=v1.w;
        }
        #pragma unroll
        for (int i = 0; i < 16; i++)
            a2[i] = __floats2half2_rn(a0v[i], a1v[i]);
    }

    const __half2 zero2 = __float2half2_rn(0.0f);

    #pragma unroll 1
    for (int l = 0; l < NL; l++) {
        const __half2* W = &sw[l*LSTRIDE];
        __half2 za = W[288];        // b2 once
        __half2 zb = zero2;
        #pragma unroll
        for (int j = 0; j < 16; j += 2) {
            // two hidden units in flight -> 2 independent HFMA2 chains
            const uint4* wa4 = (const uint4*)&W[j*16];
            const uint4* wb4 = (const uint4*)&W[(j+1)*16];
            __half2 ta = W[256+j];
            __half2 tb = W[256+j+1];
            #pragma unroll
            for (int i4 = 0; i4 < 4; i4++) {
                uint4 ua = wa4[i4];
                uint4 ub = wb4[i4];
                ta = __hfma2(a2[i4*4+0], *(__half2*)&ua.x, ta);
                tb = __hfma2(a2[i4*4+0], *(__half2*)&ub.x, tb);
                ta = __hfma2(a2[i4*4+1], *(__half2*)&ua.y, ta);
                tb = __hfma2(a2[i4*4+1], *(__half2*)&ub.y, tb);
                ta = __hfma2(a2[i4*4+2], *(__half2*)&ua.z, ta);
                tb = __hfma2(a2[i4*4+2], *(__half2*)&ub.z, tb);
                ta = __hfma2(a2[i4*4+3], *(__half2*)&ua.w, ta);
                tb = __hfma2(a2[i4*4+3], *(__half2*)&ub.w, tb);
            }
            ta = __hmax2(ta, zero2);
            tb = __hmax2(tb, zero2);
            za = __hfma2(ta, W[272+j],   za);
            zb = __hfma2(tb, W[272+j+1], zb);
        }
        float2 f = __half22float2(__hadd2(za, zb));
        float2 ewv;
        ewv.x = 1.0f / (1.0f + __expf(-f.x));
        ewv.y = 1.0f / (1.0f + __expf(-f.y));
        *(float2*)(g_ew + l*NE + p0) = ewv;
        atomicAdd(&g_deg[d0*16 + l], ewv.x);
        atomicAdd(&g_deg[d1*16 + l], ewv.y);
    }
}

// scale ew by rsqrt(deg_src) ONLY (dst factor applied in k_agg); also re-zero g_cnt
__global__ void k_norm() {
    int p = blockIdx.x*256 + threadIdx.x;   // always < NE
    if (p < NN) g_cnt[p] = 0;               // restore invariant for next replay
    int s = g_csrc[p];
    float ds[16];
    const float4* sp = (const float4*)(g_deg + s*16);
    #pragma unroll
    for (int q = 0; q < 4; q++) {
        float4 v = sp[q];
        ds[4*q]=rsqrtf(v.x); ds[4*q+1]=rsqrtf(v.y);
        ds[4*q+2]=rsqrtf(v.z); ds[4*q+3]=rsqrtf(v.w);
    }
    #pragma unroll
    for (int l = 0; l < NL; l++)
        g_ew[l*NE + p] *= ds[l];
}

// ---------------- fused BN+ReLU + tensor-core GEMM (wmma m16n16k16) ----------------
// block = 256 threads (8 warps), 128 rows; each warp: 16 rows x 64 cols
__global__ __launch_bounds__(256) void k_gemm(
    const float* __restrict__ A, const float* __restrict__ W,
    __half* __restrict__ H, int slot)     // slot < 0 : no BN
{
    __shared__ __align__(32) __half sA[128*64];   // 16 KB, fp16 BN-relu'd A tile
    __shared__ __align__(32) __half sW[64*64];    // 8 KB,  fp16 weights (k-major [k][n])
    __shared__ __align__(32) float  sC[8][16*64]; // 32 KB, per-warp fp32 C staging
    __shared__ float smu[64], ssc[64];

    int t = threadIdx.x;
    int base = blockIdx.x*128;

    if (slot >= 0 && t < 64) {
        float mu  = g_colsum[slot*64 + t] * (1.0f/NN);
        float var = g_colsq[slot*64 + t] * (1.0f/NN) - mu*mu;
        if (var < 0.0f) var = 0.0f;
        smu[t] = mu;
        ssc[t] = rsqrtf(var + 1e-5f);
    }
    // weights -> fp16 smem (no dependence on smu)
    {
        const float4* W4 = (const float4*)W;
        for (int i = t; i < 1024; i += 256) {
            float4 v = W4[i];
            __half2 h0 = __floats2half2_rn(v.x, v.y);
            __half2 h1 = __floats2half2_rn(v.z, v.w);
            uint2 u; u.x = *(unsigned*)&h0; u.y = *(unsigned*)&h1;
            *(uint2*)(sW + i*4) = u;
        }
    }
    __syncthreads();   // smu ready for A staging

    // stage A tile: BN+ReLU+fp16 via float4 loads (8 per thread)
    {
        const float4* A4 = (const float4*)A;
        const int maxi = ((NN - base < 128 ? NN - base : 128) * 64) >> 2;  // valid float4s
        for (int i = t; i < 2048; i += 256) {
            float4 v;
            if (i < maxi) v = A4[(size_t)base*16 + i];
            else { v.x = v.y = v.z = v.w = 0.0f; }
            if (slot >= 0) {
                int c = (i & 15)*4;
                v.x = fmaxf((v.x - smu[c+0]) * ssc[c+0], 0.0f);
                v.y = fmaxf((v.y - smu[c+1]) * ssc[c+1], 0.0f);
                v.z = fmaxf((v.z - smu[c+2]) * ssc[c+2], 0.0f);
                v.w = fmaxf((v.w - smu[c+3]) * ssc[c+3], 0.0f);
            }
            __half2 h0 = __floats2half2_rn(v.x, v.y);
            __half2 h1 = __floats2half2_rn(v.z, v.w);
            uint2 u; u.x = *(unsigned*)&h0; u.y = *(unsigned*)&h1;
            *(uint2*)(sA + i*4) = u;
        }
    }
    __syncthreads();

    int w = t >> 5;
    int lane = t & 31;

    wmma::fragment<wmma::accumulator, 16, 16, 16, float> acc[4];
    #pragma unroll
    for (int n = 0; n < 4; n++) wmma::fill_fragment(acc[n], 0.0f);

    #pragma unroll
    for (int k = 0; k < 4; k++) {
        wmma::fragment<wmma::matrix_a, 16, 16, 16, __half, wmma::row_major> af;
        wmma::load_matrix_sync(af, sA + (w*16)*64 + k*16, 64);
        #pragma unroll
        for (int n = 0; n < 4; n++) {
            wmma::fragment<wmma::matrix_b, 16, 16, 16, __half, wmma::row_major> bf;
            wmma::load_matrix_sync(bf, sW + (k*16)*64 + n*16, 64);
            wmma::mma_sync(acc[n], af, bf, acc[n]);
        }
    }

    // stage fp32 -> smem (per-warp private region), then fp16 coalesced store
    #pragma unroll
    for (int n = 0; n < 4; n++)
        wmma::store_matrix_sync(&sC[w][n*16], acc[n], 64, wmma::mem_row_major);

    int wrow = base + w*16;
    if (wrow < NN) {   // NN % 16 == 0, so warp tiles are all-or-nothing
        __half2* H2 = (__half2*)(H + (size_t)wrow*64);
        #pragma unroll
        for (int i = lane; i < 512; i += 32) {
            float x0 = sC[w][2*i], x1 = sC[w][2*i+1];
            H2[i] = __floats2half2_rn(x0, x1);
        }
    }
}

// ---------------- BN statistics (standalone; fp32 partials -> float atomics) ----------------
__global__ void k_bnstats(const float* __restrict__ A, int slot) {
    int t = threadIdx.x;
    int c = t & 63, rg = t >> 6;              // 256 threads: 4 row lanes x 64 cols
    float s = 0.0f, q = 0.0f;                 // ~49 elements per thread: fp32 is exact enough
    for (int r = blockIdx.x*4 + rg; r < NN; r += gridDim.x*4) {
        float v = A[r*64 + c];
        s += v; q = fmaf(v, v, q);
    }
    __shared__ float ss[256], sq[256];
    ss[t] = s; sq[t] = q; __syncthreads();
    if (t < 64) {
        float S = ss[t] + ss[t+64] + ss[t+128] + ss[t+192];
        float Q = sq[t] + sq[t+64] + sq[t+128] + sq[t+192];
        atomicAdd(&g_colsum[slot*64 + c], S);
        atomicAdd(&g_colsq [slot*64 + c], Q);
    }
}

// ---------------- CSR aggregation: LDG.128 gathers + fused elementwise epilogues ----------
// lane = (edge slot 0-3)*8 + (col group 0-7); each lane covers 8 fp16 cols.
// weights in nrm are ew*dis_src; self term weight dv (seeded by eg==0 ONLY);
// final result = dv*sum + bias, dv = rsqrt(deg_dst).
__global__ __launch_bounds__(256) void k_agg(
    const __half* __restrict__ h, const float* __restrict__ nrm,
    int layer, const float* __restrict__ bias,
    float* __restrict__ cur, float* __restrict__ acc,
    const int* __restrict__ batch, int mode)
{
    int t = threadIdx.x;
    int w = (blockIdx.x*256 + t) >> 5;     // < NN always (exact grid)
    int lane = t & 31;
    int eg = lane >> 3;          // edge slot 0..3
    int cg = lane & 7;           // col group 0..7
    int cbase = cg*8;

    float dv = rsqrtf(g_deg[w*16 + layer]);   // dis_dst

    float a[8] = {0,0,0,0,0,0,0,0};
    if (eg == 0) {   // self term seeded ONCE (reduction sums over the 4 edge slots)
        uint4 hv = *(const uint4*)(h + (size_t)w*64 + cbase);
        const __half2* hh = (const __half2*)&hv;
        #pragma unroll
        for (int i = 0; i < 4; i++) {
            float2 f = __half22float2(hh[i]);
            a[2*i]   = dv * f.x;
            a[2*i+1] = dv * f.y;
        }
    }

    int p0 = g_rowptr[w], p1 = g_rowptr[w+1];
    for (int p = p0; p < p1; p += 4) {
        int ei = p + eg;
        bool valid = (ei < p1);
        int eidx = valid ? ei : p;
        float wt = nrm[eidx];
        if (!valid) wt = 0.0f;
        int s = g_csrc[eidx];
        uint4 hv = *(const uint4*)(h + (size_t)s*64 + cbase);
        const __half2* hh = (const __half2*)&hv;
        #pragma unroll
        for (int i = 0; i < 4; i++) {
            float2 f = __half22float2(hh[i]);
            a[2*i]   = fmaf(wt, f.x, a[2*i]);
            a[2*i+1] = fmaf(wt, f.y, a[2*i+1]);
        }
    }

    // reduce across the 4 edge slots (lanes cg, cg+8, cg+16, cg+24)
    #pragma unroll
    for (int i = 0; i < 8; i++) {
        a[i] += __shfl_xor_sync(0xffffffffu, a[i], 8);
        a[i] += __shfl_xor_sync(0xffffffffu, a[i], 16);
    }

    if (lane < 8) {
        float4 b0 = *(const float4*)(bias + cbase);
        float4 b1 = *(const float4*)(bias + cbase + 4);
        float o[8];
        o[0] = fmaf(dv, a[0], b0.x); o[1] = fmaf(dv, a[1], b0.y);
        o[2] = fmaf(dv, a[2], b0.z); o[3] = fmaf(dv, a[3], b0.w);
        o[4] = fmaf(dv, a[4], b1.x); o[5] = fmaf(dv, a[5], b1.y);
        o[6] = fmaf(dv, a[6], b1.z); o[7] = fmaf(dv, a[7], b1.w);

        size_t off = (size_t)w*64 + cbase;
        if (mode & M_SKIP) {
            float4 s0 = *(float4*)(acc + off);
            float4 s1 = *(float4*)(acc + off + 4);
            o[0] += s0.x; o[1] += s0.y; o[2] += s0.z; o[3] += s0.w;
            o[4] += s1.x; o[5] += s1.y; o[6] += s1.z; o[7] += s1.w;
            s0.x += o[0]; s0.y += o[1]; s0.z += o[2]; s0.w += o[3];
            s1.x += o[4]; s1.y += o[5]; s1.z += o[6]; s1.w += o[7];
            *(float4*)(acc + off)     = s0;
            *(float4*)(acc + off + 4) = s1;
        }
        float4 c0, c1;
        c0.x=o[0]; c0.y=o[1]; c0.z=o[2]; c0.w=o[3];
        c1.x=o[4]; c1.y=o[5]; c1.z=o[6]; c1.w=o[7];
        *(float4*)(cur + off)     = c0;
        *(float4*)(cur + off + 4) = c1;
        if (mode & M_COPY) {
            *(float4*)(acc + off)     = c0;
            *(float4*)(acc + off + 4) = c1;
        }
        if (mode & M_POOL) {
            int b = batch[w];
            #pragma unroll
            for (int i = 0; i < 8; i++) {
                float rv = fmaxf(o[i], 0.0f);
                atomicMax((int*)&g_pool[b*64 + cbase + i], __float_as_int(rv));
            }
        }
    }
}

// ---------------- readout ----------------
__global__ void k_final(const float* __restrict__ linW, const float* __restrict__ linb,
                        float* __restrict__ out) {
    int g = blockIdx.x*blockDim.x + threadIdx.x;
    if (g >= NG) return;
    float a0 = linb[0], a1 = linb[1];
    #pragma unroll 8
    for (int c = 0; c < CC; c++) {
        float v = g_pool[g*64 + c];
        a0 = fmaf(v, linW[c*2+0], a0);
        a1 = fmaf(v, linW[c*2+1], a1);
    }
    out[g*2+0] = a0;
    out[g*2+1] = a1;
}

// ---------------- launch ----------------
extern "C" void kernel_launch(void* const* d_in, const int* in_sizes, int n_in,
                              void* d_out, int out_size)
{
    const float* x     = (const float*)d_in[0];
    const int*   ei    = (const int*)  d_in[1];
    const int*   batch = (const int*)  d_in[2];
    /* d_in[3] = dropout (unused, eval mode) */
    const float* ea    = (const float*)d_in[4];
    const float* Wlin1 = (const float*)d_in[5];
    const float* bias1 = (const float*)d_in[6];
    const float* m1W1  = (const float*)d_in[7];
    const float* m1b1  = (const float*)d_in[8];
    const float* m2W1  = (const float*)d_in[9];
    const float* m2b1  = (const float*)d_in[10];
    const float* hWlin = (const float*)d_in[11];
    const float* hbias = (const float*)d_in[12];
    const float* hm1W  = (const float*)d_in[13];
    const float* hm1b  = (const float*)d_in[14];
    const float* hm2W  = (const float*)d_in[15];
    const float* hm2b  = (const float*)d_in[16];
    const float* linW  = (const float*)d_in[17];
    const float* linb  = (const float*)d_in[18];
    float* out = (float*)d_out;

    const int* src = ei;
    const int* dst = ei + NE;

    __half *p_h;
    float *p_cur, *p_acc, *p_ew;
    cudaGetSymbolAddress((void**)&p_h,   g_h);
    cudaGetSymbolAddress((void**)&p_cur, g_cur);
    cudaGetSymbolAddress((void**)&p_acc, g_acc);
    cudaGetSymbolAddress((void**)&p_ew,  g_ew);

    const int EB = NE / 256;                  // 3125 (exact)
    const int MB = (NE/2 + 255) / 256;        // 1563 (edgemlp, 2 edges/thread)
    const int GB = (NN + 127) / 128;          // 391 (gemm, 128 rows/block)
    const int AB = (NN*32) / 256;             // 6250 (exact -> 50000 warps = NN)

    // prologue: CSR + all edge norms for all 13 layers
    k_hist   <<<EB, 256>>>(dst);              // also inits g_deg=1.0
    k_scanall<<<1, 1024>>>();                 // also zeroes pool + BN stats
    k_scatter<<<EB, 256>>>(src, dst);
    k_edgemlp<<<MB, 256>>>(ea, m1W1, m1b1, m2W1, m2b1, hm1W, hm1b, hm2W, hm2b);
    k_norm   <<<EB, 256>>>();                 // rsqrt on the fly; also re-zeroes g_cnt

    // conv1
    k_gemm<<<GB, 256>>>(x, Wlin1, p_h, -1);
    k_agg <<<AB, 256>>>(p_h, p_ew, 0, bias1, p_cur, p_acc, batch, M_COPY);

    // 12 hidden convs (6 blocks x 2)
    for (int j = 0; j < 12; j++) {
        int l = j + 1;
        k_bnstats<<<256, 256>>>(p_cur, j);
        k_gemm<<<GB, 256>>>(p_cur, hWlin + j*CC*CC, p_h, j);
        int mode;
        if (j == 11)      mode = M_SKIP | M_POOL;   // last: skip + relu + pool
        else if (j & 1)   mode = M_SKIP;            // end of block: dense skip
        else              mode = 0;
        k_agg <<<AB, 256>>>(p_h, p_ew + l*NE, l, hbias + j*CC, p_cur, p_acc, batch, mode);
    }

    k_final<<<(NG + 63)/64, 64>>>(linW, linb, out);
}